// round 16
// baseline (speedup 1.0000x reference)
#include <cuda_runtime.h>
#include <cuda_bf16.h>

#define N_NODES  100000
#define N_EDGES  1200000
#define N_GRAPHS 256
#define SCAN_BLOCKS 98     // node chunks of 1024
#define CSR_BLOCKS  148    // persistent grid; co-resident by construction
#define GT (CSR_BLOCKS * 1024)

// ---------------- device scratch (no allocs allowed) ----------------
// Contract: g_deg, g_poolM, g_poolS, g_cnt, g_bar are ZERO on entry to
// kernel_launch (zero-init on module load; csr_kernel re-zeroes g_deg,
// mlp_kernel re-zeroes the rest) -> deterministic graph replay.
__device__ int   g_deg[N_NODES];
__device__ int   g_rowptr[N_NODES + 1];
__device__ int   g_cur[N_NODES];
__device__ int   g_csr[N_EDGES];
__device__ int   g_bsums[SCAN_BLOCKS];
__device__ int   g_bar;
__device__ __align__(16) float g_h1[N_NODES * 64];
__device__ __align__(16) float g_h2[N_NODES * 64];
__device__ __align__(16) float g_poolM[N_GRAPHS * 64];  // sum of mean3 rows
__device__ __align__(16) float g_poolS[N_GRAPHS * 64];  // sum of h2 rows
__device__ int   g_cnt[N_GRAPHS];                       // nodes per graph

// ---------------- fused CSR build: count -> scan -> fill ------------------
// One persistent launch, 148 blocks x 1024 threads (<=1 block/SM guaranteed
// resident), spin grid-barriers between phases. Edge phases are grid-stride
// with x4 manual unroll for memory-level parallelism.
__device__ __forceinline__ void grid_bar(int phase) {
    __threadfence();
    __syncthreads();
    if (threadIdx.x == 0) {
        atomicAdd(&g_bar, 1);
        while (*(volatile int*)&g_bar < phase * CSR_BLOCKS) { }
    }
    __syncthreads();
    __threadfence();
}

__global__ void __launch_bounds__(1024) csr_kernel(const int* __restrict__ edge) {
    __shared__ int s[1024];
    __shared__ int s2[128];
    const int tid = threadIdx.x;
    const int gtid = blockIdx.x * 1024 + tid;

    // ---- phase 1: degree count (RED, no return; x4 unrolled) ----
    {
        int e = gtid;
        for (; e + 3 * GT < N_EDGES; e += 4 * GT) {
            int d0 = edge[N_EDGES + e];
            int d1 = edge[N_EDGES + e + GT];
            int d2 = edge[N_EDGES + e + 2 * GT];
            int d3 = edge[N_EDGES + e + 3 * GT];
            atomicAdd(&g_deg[d0], 1);
            atomicAdd(&g_deg[d1], 1);
            atomicAdd(&g_deg[d2], 1);
            atomicAdd(&g_deg[d3], 1);
        }
        for (; e < N_EDGES; e += GT)
            atomicAdd(&g_deg[edge[N_EDGES + e]], 1);
    }
    grid_bar(1);

    // ---- phase 2a: per-chunk scan (blocks 0..97 own node chunks) ----
    int local_excl = 0;
    const int i = blockIdx.x * 1024 + tid;   // node index for scan blocks
    if (blockIdx.x < SCAN_BLOCKS) {
        int v = (i < N_NODES) ? g_deg[i] : 0;
        s[tid] = v;
        __syncthreads();
        for (int off = 1; off < 1024; off <<= 1) {
            int t = (tid >= off) ? s[tid - off] : 0;
            __syncthreads();
            s[tid] += t;
            __syncthreads();
        }
        local_excl = s[tid] - v;
        if (tid == 1023) g_bsums[blockIdx.x] = s[1023];
    }
    grid_bar(2);

    // ---- phase 2b: top-level prefix (recomputed per block) + rowptr ----
    if (blockIdx.x < SCAN_BLOCKS) {
        if (tid < 128) s2[tid] = (tid < SCAN_BLOCKS) ? g_bsums[tid] : 0;
        __syncthreads();
        for (int off = 1; off < 128; off <<= 1) {
            int t = (tid < 128 && tid >= off) ? s2[tid - off] : 0;
            __syncthreads();
            if (tid < 128) s2[tid] += t;
            __syncthreads();
        }
        int boff = (blockIdx.x == 0) ? 0 : s2[blockIdx.x - 1];
        if (i < N_NODES) {
            int r = local_excl + boff;
            g_rowptr[i] = r;
            g_cur[i] = r;
            g_deg[i] = 0;                  // reset for next replay
        }
        if (i == 0) g_rowptr[N_NODES] = N_EDGES;
    }
    grid_bar(3);

    // ---- phase 3: fill (x4 unrolled: 4 independent atomic->store chains) --
    {
        int e = gtid;
        for (; e + 3 * GT < N_EDGES; e += 4 * GT) {
            int s0 = edge[e],          d0 = edge[N_EDGES + e];
            int s1 = edge[e + GT],     d1 = edge[N_EDGES + e + GT];
            int s2e = edge[e + 2 * GT], d2 = edge[N_EDGES + e + 2 * GT];
            int s3 = edge[e + 3 * GT], d3 = edge[N_EDGES + e + 3 * GT];
            int p0 = atomicAdd(&g_cur[d0], 1);
            int p1 = atomicAdd(&g_cur[d1], 1);
            int p2 = atomicAdd(&g_cur[d2], 1);
            int p3 = atomicAdd(&g_cur[d3], 1);
            g_csr[p0] = s0;
            g_csr[p1] = s1;
            g_csr[p2] = s2e;
            g_csr[p3] = s3;
        }
        for (; e < N_EDGES; e += GT) {
            int src = edge[e];
            int dst = edge[N_EDGES + e];
            int pos = atomicAdd(&g_cur[dst], 1);
            g_csr[pos] = src;
        }
    }
}

// ---------------- layer 1: x[100k,8] -> g_h1[100k,64], relu ----------------
#define A8_STRIDE 20
__global__ void sage8_kernel(const float* __restrict__ x,
                             const float* __restrict__ Wl,
                             const float* __restrict__ bias,
                             const float* __restrict__ Wr) {
    __shared__ __align__(16) float sA[128 * A8_STRIDE];
    __shared__ float sB[16 * 64];
    __shared__ float sBias[64];

    const int tid = threadIdx.x;
    if (tid < 128) ((float4*)sB)[tid] = ((const float4*)Wl)[tid];
    else           ((float4*)sB)[tid] = ((const float4*)Wr)[tid - 128];
    if (tid < 64) sBias[tid] = bias[tid];

    const int base = blockIdx.x * 128;
    const float4* x4 = (const float4*)x;

    {
        const int lane = tid & 31;
        const int nodeLocal = (tid >> 5) * 16 + (lane >> 1);
        const int p = lane & 1;
        const int node = base + nodeLocal;
        float4 m  = make_float4(0.f, 0.f, 0.f, 0.f);
        float4 sf = make_float4(0.f, 0.f, 0.f, 0.f);
        if (node < N_NODES) {
            int start = g_rowptr[node], end = g_rowptr[node + 1];
            float4 a0 = make_float4(0.f, 0.f, 0.f, 0.f);
            float4 a1 = make_float4(0.f, 0.f, 0.f, 0.f);
            float4 a2 = make_float4(0.f, 0.f, 0.f, 0.f);
            float4 a3 = make_float4(0.f, 0.f, 0.f, 0.f);
            int e = start;
            for (; e + 3 < end; e += 4) {
                int s0 = g_csr[e],     s1 = g_csr[e + 1];
                int s2 = g_csr[e + 2], s3 = g_csr[e + 3];
                float4 v0 = x4[s0 * 2 + p];
                float4 v1 = x4[s1 * 2 + p];
                float4 v2 = x4[s2 * 2 + p];
                float4 v3 = x4[s3 * 2 + p];
                a0.x += v0.x; a0.y += v0.y; a0.z += v0.z; a0.w += v0.w;
                a1.x += v1.x; a1.y += v1.y; a1.z += v1.z; a1.w += v1.w;
                a2.x += v2.x; a2.y += v2.y; a2.z += v2.z; a2.w += v2.w;
                a3.x += v3.x; a3.y += v3.y; a3.z += v3.z; a3.w += v3.w;
            }
            for (; e < end; ++e) {
                float4 v0 = x4[g_csr[e] * 2 + p];
                a0.x += v0.x; a0.y += v0.y; a0.z += v0.z; a0.w += v0.w;
            }
            float inv = 1.0f / (float)max(end - start, 1);
            m.x = (a0.x + a1.x + a2.x + a3.x) * inv;
            m.y = (a0.y + a1.y + a2.y + a3.y) * inv;
            m.z = (a0.z + a1.z + a2.z + a3.z) * inv;
            m.w = (a0.w + a1.w + a2.w + a3.w) * inv;
            sf = x4[node * 2 + p];
        }
        *(float4*)&sA[nodeLocal * A8_STRIDE + p * 4]     = m;
        *(float4*)&sA[nodeLocal * A8_STRIDE + 8 + p * 4] = sf;
    }
    __syncthreads();

    const int tn = tid & 15, tm = tid >> 4;
    float acc[8][4];
#pragma unroll
    for (int i = 0; i < 8; ++i)
#pragma unroll
        for (int j = 0; j < 4; ++j) acc[i][j] = sBias[tn * 4 + j];

#pragma unroll
    for (int k = 0; k < 16; ++k) {
        float4 bv = *(const float4*)&sB[k * 64 + tn * 4];
        float a[8];
#pragma unroll
        for (int i = 0; i < 8; ++i) a[i] = sA[(tm * 8 + i) * A8_STRIDE + k];
#pragma unroll
        for (int i = 0; i < 8; ++i) {
            acc[i][0] += a[i] * bv.x;
            acc[i][1] += a[i] * bv.y;
            acc[i][2] += a[i] * bv.z;
            acc[i][3] += a[i] * bv.w;
        }
    }

    float4* hout4 = (float4*)g_h1;
#pragma unroll
    for (int i = 0; i < 8; ++i) {
        int node = base + tm * 8 + i;
        if (node < N_NODES) {
            float4 o;
            o.x = fmaxf(acc[i][0], 0.0f);
            o.y = fmaxf(acc[i][1], 0.0f);
            o.z = fmaxf(acc[i][2], 0.0f);
            o.w = fmaxf(acc[i][3], 0.0f);
            hout4[node * 16 + tn] = o;
        }
    }
}

// ---------------- layer 2: g_h1 -> g_h2, relu (R8/R11 GEMM) ---------------
#define TILE_N64 112
#define A_STRIDE 68   // 272 B rows, 16B-aligned
#define SM64_BYTES ((TILE_N64 * A_STRIDE + 2 * 4096) * 4)   // 63232

__global__ void __launch_bounds__(256) sage64_kernel(
                              const float* __restrict__ Wl,
                              const float* __restrict__ bias,
                              const float* __restrict__ Wr) {
    extern __shared__ float sm64[];
    float* sA  = sm64;                              // [112][68]
    float* sBl = sm64 + TILE_N64 * A_STRIDE;        // [64][64]
    float* sBr = sBl + 4096;                        // [64][64]

    const float* hin = g_h1;
    float* hout      = g_h2;

    const int tid  = threadIdx.x;
    const int base = blockIdx.x * TILE_N64;
    const int warp = tid >> 5, lane = tid & 31;
    const int lr = lane >> 4;
    const int hl = lane & 15;

    {
        const float4* Wl4 = (const float4*)Wl;
        const float4* Wr4 = (const float4*)Wr;
        float4* l4 = (float4*)sBl;
        float4* r4 = (float4*)sBr;
#pragma unroll
        for (int t = 0; t < 4; ++t) {
            l4[tid + t * 256] = Wl4[tid + t * 256];
            r4[tid + t * 256] = Wr4[tid + t * 256];
        }
    }
    __syncthreads();

    const float4* hin4 = (const float4*)hin;
    const int rowBase = warp * 14 + lr * 7;

    for (int it = 0; it < 7; ++it) {
        int nodeLocal = rowBase + it;
        int node = base + nodeLocal;
        float4 m = make_float4(0.f, 0.f, 0.f, 0.f);
        if (node < N_NODES) {
            int start = g_rowptr[node], end = g_rowptr[node + 1];
            float4 a0 = make_float4(0.f, 0.f, 0.f, 0.f);
            float4 a1 = make_float4(0.f, 0.f, 0.f, 0.f);
            float4 a2 = make_float4(0.f, 0.f, 0.f, 0.f);
            float4 a3 = make_float4(0.f, 0.f, 0.f, 0.f);
            int e = start;
            for (; e + 3 < end; e += 4) {
                int s0 = g_csr[e],     s1 = g_csr[e + 1];
                int s2 = g_csr[e + 2], s3 = g_csr[e + 3];
                float4 v0 = hin4[s0 * 16 + hl];
                float4 v1 = hin4[s1 * 16 + hl];
                float4 v2 = hin4[s2 * 16 + hl];
                float4 v3 = hin4[s3 * 16 + hl];
                a0.x += v0.x; a0.y += v0.y; a0.z += v0.z; a0.w += v0.w;
                a1.x += v1.x; a1.y += v1.y; a1.z += v1.z; a1.w += v1.w;
                a2.x += v2.x; a2.y += v2.y; a2.z += v2.z; a2.w += v2.w;
                a3.x += v3.x; a3.y += v3.y; a3.z += v3.z; a3.w += v3.w;
            }
            for (; e < end; ++e) {
                int s0 = g_csr[e];
                float4 v0 = hin4[s0 * 16 + hl];
                a0.x += v0.x; a0.y += v0.y; a0.z += v0.z; a0.w += v0.w;
            }
            float inv = 1.0f / (float)max(end - start, 1);
            m.x = (a0.x + a1.x + a2.x + a3.x) * inv;
            m.y = (a0.y + a1.y + a2.y + a3.y) * inv;
            m.z = (a0.z + a1.z + a2.z + a3.z) * inv;
            m.w = (a0.w + a1.w + a2.w + a3.w) * inv;
        }
        *(float4*)&sA[nodeLocal * A_STRIDE + hl * 4] = m;
    }
    __syncwarp();

    float acc[7][4];
    {
        float4 bb = *(const float4*)&bias[hl * 4];
#pragma unroll
        for (int i = 0; i < 7; ++i) {
            acc[i][0] = bb.x; acc[i][1] = bb.y; acc[i][2] = bb.z; acc[i][3] = bb.w;
        }
    }

#pragma unroll 4
    for (int k = 0; k < 64; k += 2) {
        float4 bv0 = *(const float4*)&sBl[k * 64 + hl * 4];
        float4 bv1 = *(const float4*)&sBl[(k + 1) * 64 + hl * 4];
        float2 a[7];
#pragma unroll
        for (int i = 0; i < 7; ++i)
            a[i] = *(const float2*)&sA[(rowBase + i) * A_STRIDE + k];
#pragma unroll
        for (int i = 0; i < 7; ++i) {
            acc[i][0] += a[i].x * bv0.x; acc[i][1] += a[i].x * bv0.y;
            acc[i][2] += a[i].x * bv0.z; acc[i][3] += a[i].x * bv0.w;
            acc[i][0] += a[i].y * bv1.x; acc[i][1] += a[i].y * bv1.y;
            acc[i][2] += a[i].y * bv1.z; acc[i][3] += a[i].y * bv1.w;
        }
    }
    __syncwarp();

#pragma unroll
    for (int t = 0; t < 7; ++t) {
        int idx = lane + t * 32;
        int nl = idx >> 4, c = idx & 15;
        int nodeLocal = warp * 14 + nl;
        int node = base + nodeLocal;
        float4 v = make_float4(0.f, 0.f, 0.f, 0.f);
        if (node < N_NODES) v = hin4[node * 16 + c];
        *(float4*)&sA[nodeLocal * A_STRIDE + c * 4] = v;
    }
    __syncwarp();

#pragma unroll 4
    for (int k = 0; k < 64; k += 2) {
        float4 bv0 = *(const float4*)&sBr[k * 64 + hl * 4];
        float4 bv1 = *(const float4*)&sBr[(k + 1) * 64 + hl * 4];
        float2 a[7];
#pragma unroll
        for (int i = 0; i < 7; ++i)
            a[i] = *(const float2*)&sA[(rowBase + i) * A_STRIDE + k];
#pragma unroll
        for (int i = 0; i < 7; ++i) {
            acc[i][0] += a[i].x * bv0.x; acc[i][1] += a[i].x * bv0.y;
            acc[i][2] += a[i].x * bv0.z; acc[i][3] += a[i].x * bv0.w;
            acc[i][0] += a[i].y * bv1.x; acc[i][1] += a[i].y * bv1.y;
            acc[i][2] += a[i].y * bv1.z; acc[i][3] += a[i].y * bv1.w;
        }
    }

    float4* hout4 = (float4*)hout;
#pragma unroll
    for (int i = 0; i < 7; ++i) {
        int node = base + rowBase + i;
        if (node < N_NODES) {
            float4 o;
            o.x = fmaxf(acc[i][0], 0.f); o.y = fmaxf(acc[i][1], 0.f);
            o.z = fmaxf(acc[i][2], 0.f); o.w = fmaxf(acc[i][3], 0.f);
            hout4[node * 16 + hl] = o;
        }
    }
}

// ---------------- layer 3 (linear) + pool: gather-only --------------------
__global__ void __launch_bounds__(256) pool3_kernel(const int* __restrict__ batch) {
    const int tid = threadIdx.x;
    const int base = blockIdx.x * 128;
    const int warp = tid >> 5, lane = tid & 31;
    const int half = lane >> 4, hl = lane & 15;
    const float4* hin4 = (const float4*)g_h2;

    int cur = -1, cnt = 0;
    float4 sM = make_float4(0.f, 0.f, 0.f, 0.f);
    float4 sS = make_float4(0.f, 0.f, 0.f, 0.f);

    for (int it = 0; it < 8; ++it) {
        int node = base + warp * 16 + it * 2 + half;
        if (node >= N_NODES) break;

        int start = g_rowptr[node], end = g_rowptr[node + 1];
        float4 a0 = make_float4(0.f, 0.f, 0.f, 0.f);
        float4 a1 = make_float4(0.f, 0.f, 0.f, 0.f);
        float4 a2 = make_float4(0.f, 0.f, 0.f, 0.f);
        float4 a3 = make_float4(0.f, 0.f, 0.f, 0.f);
        int e = start;
        for (; e + 3 < end; e += 4) {
            int s0 = g_csr[e],     s1 = g_csr[e + 1];
            int s2 = g_csr[e + 2], s3 = g_csr[e + 3];
            float4 v0 = hin4[s0 * 16 + hl];
            float4 v1 = hin4[s1 * 16 + hl];
            float4 v2 = hin4[s2 * 16 + hl];
            float4 v3 = hin4[s3 * 16 + hl];
            a0.x += v0.x; a0.y += v0.y; a0.z += v0.z; a0.w += v0.w;
            a1.x += v1.x; a1.y += v1.y; a1.z += v1.z; a1.w += v1.w;
            a2.x += v2.x; a2.y += v2.y; a2.z += v2.z; a2.w += v2.w;
            a3.x += v3.x; a3.y += v3.y; a3.z += v3.z; a3.w += v3.w;
        }
        for (; e < end; ++e) {
            float4 v0 = hin4[g_csr[e] * 16 + hl];
            a0.x += v0.x; a0.y += v0.y; a0.z += v0.z; a0.w += v0.w;
        }
        float inv = 1.0f / (float)max(end - start, 1);
        float4 m;
        m.x = (a0.x + a1.x + a2.x + a3.x) * inv;
        m.y = (a0.y + a1.y + a2.y + a3.y) * inv;
        m.z = (a0.z + a1.z + a2.z + a3.z) * inv;
        m.w = (a0.w + a1.w + a2.w + a3.w) * inv;
        float4 sf = hin4[node * 16 + hl];

        int b = batch[node];
        if (b != cur) {
            if (cur >= 0) {
                float* dM = &g_poolM[cur * 64 + hl * 4];
                float* dS = &g_poolS[cur * 64 + hl * 4];
                atomicAdd(dM + 0, sM.x); atomicAdd(dM + 1, sM.y);
                atomicAdd(dM + 2, sM.z); atomicAdd(dM + 3, sM.w);
                atomicAdd(dS + 0, sS.x); atomicAdd(dS + 1, sS.y);
                atomicAdd(dS + 2, sS.z); atomicAdd(dS + 3, sS.w);
                if (hl == 0) atomicAdd(&g_cnt[cur], cnt);
            }
            cur = b; cnt = 0;
            sM = make_float4(0.f, 0.f, 0.f, 0.f);
            sS = make_float4(0.f, 0.f, 0.f, 0.f);
        }
        sM.x += m.x; sM.y += m.y; sM.z += m.z; sM.w += m.w;
        sS.x += sf.x; sS.y += sf.y; sS.z += sf.z; sS.w += sf.w;
        ++cnt;
    }
    if (cur >= 0) {
        float* dM = &g_poolM[cur * 64 + hl * 4];
        float* dS = &g_poolS[cur * 64 + hl * 4];
        atomicAdd(dM + 0, sM.x); atomicAdd(dM + 1, sM.y);
        atomicAdd(dM + 2, sM.z); atomicAdd(dM + 3, sM.w);
        atomicAdd(dS + 0, sS.x); atomicAdd(dS + 1, sS.y);
        atomicAdd(dS + 2, sS.z); atomicAdd(dS + 3, sS.w);
        if (hl == 0) atomicAdd(&g_cnt[cur], cnt);
    }
}

// ---------------- MLP head: layer-3 GEMM on pooled vectors + classifier ---
__global__ void mlp_kernel(const float* __restrict__ W3l,
                           const float* __restrict__ b3,
                           const float* __restrict__ W3r,
                           const float* __restrict__ Wc1,
                           const float* __restrict__ bc1,
                           const float* __restrict__ Wc2,
                           const float* __restrict__ bc2,
                           float* __restrict__ out) {
    __shared__ float sh[8][64];
    int warp = threadIdx.x >> 5;
    int lane = threadIdx.x & 31;
    int gr = blockIdx.x * 8 + warp;
    if (gr < N_GRAPHS) {
        float c = (float)g_cnt[gr];
        float h0 = c * b3[2 * lane];
        float h1 = c * b3[2 * lane + 1];
#pragma unroll 4
        for (int k = 0; k < 64; ++k) {
            float pm = g_poolM[gr * 64 + k];
            float ps = g_poolS[gr * 64 + k];
            h0 += pm * W3l[k * 64 + 2 * lane]     + ps * W3r[k * 64 + 2 * lane];
            h1 += pm * W3l[k * 64 + 2 * lane + 1] + ps * W3r[k * 64 + 2 * lane + 1];
        }
        sh[warp][2 * lane]     = h0;
        sh[warp][2 * lane + 1] = h1;
        __syncwarp();
        float h = bc1[lane];
#pragma unroll
        for (int k = 0; k < 64; ++k)
            h += sh[warp][k] * Wc1[k * 32 + lane];
        h = fmaxf(h, 0.0f);
        float p = h * Wc2[lane];
#pragma unroll
        for (int off = 16; off > 0; off >>= 1)
            p += __shfl_xor_sync(0xffffffffu, p, off);
        if (lane == 0) out[gr] = p + bc2[0];
        // re-zero replay state (own graph's rows; reads above complete)
        g_poolM[gr * 64 + 2 * lane]     = 0.0f;
        g_poolM[gr * 64 + 2 * lane + 1] = 0.0f;
        g_poolS[gr * 64 + 2 * lane]     = 0.0f;
        g_poolS[gr * 64 + 2 * lane + 1] = 0.0f;
        if (lane == 0) g_cnt[gr] = 0;
    }
    if (blockIdx.x == 0 && threadIdx.x == 0) g_bar = 0;
}

// ---------------- launch ----------------
extern "C" void kernel_launch(void* const* d_in, const int* in_sizes, int n_in,
                              void* d_out, int out_size) {
    const float* x     = (const float*)d_in[0];
    const int*   edge  = (const int*)d_in[1];     // int32 (JAX x64 disabled)
    const int*   batch = (const int*)d_in[2];     // int32
    const float* W1l = (const float*)d_in[3];
    const float* b1  = (const float*)d_in[4];
    const float* W1r = (const float*)d_in[5];
    const float* W2l = (const float*)d_in[6];
    const float* b2  = (const float*)d_in[7];
    const float* W2r = (const float*)d_in[8];
    const float* W3l = (const float*)d_in[9];
    const float* b3  = (const float*)d_in[10];
    const float* W3r = (const float*)d_in[11];
    const float* Wc1 = (const float*)d_in[12];
    const float* bc1 = (const float*)d_in[13];
    const float* Wc2 = (const float*)d_in[14];
    const float* bc2 = (const float*)d_in[15];
    float* out = (float*)d_out;

    cudaFuncSetAttribute(sage64_kernel,
                         cudaFuncAttributeMaxDynamicSharedMemorySize, SM64_BYTES);

    csr_kernel<<<CSR_BLOCKS, 1024>>>(edge);                        // 1

    const int NT8  = (N_NODES + 127) / 128;                // 782
    const int NT64 = (N_NODES + TILE_N64 - 1) / TILE_N64;  // 893
    sage8_kernel<<<NT8, 256>>>(x, W1l, b1, W1r);                   // 2
    sage64_kernel<<<NT64, 256, SM64_BYTES>>>(W2l, b2, W2r);        // 3
    pool3_kernel<<<NT8, 256>>>(batch);                             // 4

    mlp_kernel<<<32, 256>>>(W3l, b3, W3r, Wc1, bc1, Wc2, bc2, out);// 5
}